// round 7
// baseline (speedup 1.0000x reference)
#include <cuda_runtime.h>
#include <cstdint>

#define NB      4
#define GDIM    7
#define NREG    49
#define HH      224
#define CC      256
#define NQ      100
#define ROWS    64      // q rows per CTA (2 q-tiles)
#define THREADS 256     // 8 warps x 8 q-rows
#define KEYS    64      // keys per pass (two 32-key row strips)
#define NPASS   16
#define HSTRIDE (HH*CC) // image pixel-row stride in floats

#define KSTRIDE  260    // sK [KEYS][KSTRIDE]; 260 = 4*65 -> conflict-free lane-strided LDS.128
#define QTSTRIDE 68     // sQt [CC][QTSTRIDE] transposed queries (broadcast reads)
#define PSTRIDE  12     // sP floats per key (48B -> 3k mod 8 bank groups, conflict-free .128)

#define SK_FLOATS  (KEYS*KSTRIDE)        // 16640
#define SQT_FLOATS (CC*QTSTRIDE)         // 17408
#define SP_FLOATS  (8*KEYS*PSTRIDE)      // 6144
#define SMEM_FLOATS (2*SK_FLOATS + SQT_FLOATS + SP_FLOATS)
#define SMEM_BYTES  (SMEM_FLOATS*4)      // 227,328 B

#define OUT_ELEMS (NB*NREG*NQ*CC)
#define POS_ELEMS (NREG*2)

typedef unsigned long long u64;

// ---------------- packed f32x2 helpers ----------------
__device__ __forceinline__ u64 pack2(float a, float b) {
    u64 r; asm("mov.b64 %0, {%1, %2};" : "=l"(r) : "f"(a), "f"(b)); return r;
}
__device__ __forceinline__ void unpack2(u64 v, float& a, float& b) {
    asm("mov.b64 {%0, %1}, %2;" : "=f"(a), "=f"(b) : "l"(v));
}
__device__ __forceinline__ void fma2(u64& d, u64 a, u64 b) {
    asm("fma.rn.f32x2 %0, %1, %2, %0;" : "+l"(d) : "l"(a), "l"(b));
}
__device__ __forceinline__ void mul2(u64& d, u64 a) {
    asm("mul.rn.f32x2 %0, %1, %0;" : "+l"(d) : "l"(a));
}
__device__ __forceinline__ void add2(u64& d, u64 a) {
    asm("add.rn.f32x2 %0, %1, %0;" : "+l"(d) : "l"(a));
}

// ---------------- cp.async helpers ----------------
__device__ __forceinline__ uint32_t s2u(const void* p) {
    return (uint32_t)__cvta_generic_to_shared(p);
}
__device__ __forceinline__ void cp16(uint32_t s, const void* g) {
    asm volatile("cp.async.cg.shared.global [%0], [%1], 16;" :: "r"(s), "l"(g));
}
#define CP_COMMIT() asm volatile("cp.async.commit_group;")
#define CP_WAIT1()  asm volatile("cp.async.wait_group 1;")

// ---------------- fused attention ----------------
// grid: 392 CTAs (196 regions x 2 q-tiles), 256 threads
__global__ void __launch_bounds__(THREADS, 1)
attn_kernel(const float* __restrict__ images,
            const float* __restrict__ queries,
            float* __restrict__ out)
{
    extern __shared__ float smem[];
    float* sK0 = smem;
    float* sK1 = smem + SK_FLOATS;
    float* sQt = smem + 2*SK_FLOATS;
    float* sP  = sQt + SQT_FLOATS;

    const int bx     = blockIdx.x;
    const int region = bx >> 1;
    const int qtile  = bx & 1;
    const int b  = region / NREG;
    const int n  = region % NREG;
    const int gi = n / GDIM;
    const int gj = n % GDIM;

    const int tid  = threadIdx.x;
    const int lane = tid & 31;
    const int warp = tid >> 5;

    const float* imgbase = images + ((size_t)(b*HH + gi*32)*HH + gj*32)*CC;

    // thread-fixed copy geometry: c4 = float col, r0 = base key row
    const int cpc = (tid & 63) * 4;
    const int r0  = tid >> 6;            // 0..3
    const uint32_t sku0 = s2u(sK0);
    const uint32_t sku1 = s2u(sK1);

    // prefetch passes 0 and 1 (16 x 16B per thread each)
    #pragma unroll
    for (int k = 0; k < 16; k++) {
        int r = r0 + 4*k;
        cp16(sku0 + (r*KSTRIDE + cpc)*4,
             imgbase + (size_t)(r >> 5)*HSTRIDE + (r & 31)*CC + cpc);
    }
    CP_COMMIT();
    #pragma unroll
    for (int k = 0; k < 16; k++) {
        int r = r0 + 4*k;
        cp16(sku1 + (r*KSTRIDE + cpc)*4,
             imgbase + (size_t)(2 + (r >> 5))*HSTRIDE + (r & 31)*CC + cpc);
    }
    CP_COMMIT();

    // stage Q transposed: sQt[c][q]  (one-time; conflicts amortized)
    for (int id = tid; id < ROWS*CC; id += THREADS) {
        int q = id >> 8;
        int c = id & 255;
        int qg = qtile*ROWS + q;
        sQt[c*QTSTRIDE + q] = (qg < NQ) ? queries[qg*CC + c] : 0.0f;
    }

    float m[8];
    u64 acc2[4][8];     // acc2[rp][j] = (out[2rp], out[2rp+1]) at channel j
    u64 accl[4];        // row-sum pairs (softmax denominators)
    #pragma unroll
    for (int r = 0; r < 8; r++) m[r] = -1e30f;
    #pragma unroll
    for (int rp = 0; rp < 4; rp++) {
        accl[rp] = 0ull;
        #pragma unroll
        for (int j = 0; j < 8; j++) acc2[rp][j] = 0ull;
    }

    float* sPw = sP + warp*(KEYS*PSTRIDE);
    const float* qb = sQt + warp*8;

    for (int p = 0; p < NPASS; p++) {
        CP_WAIT1();
        __syncthreads();
        const float* sK = (p & 1) ? sK1 : sK0;

        // ---- scores: 8 rows x 64 keys (lane holds keys lane, lane+32) ----
        u64 sa01=0, sa23=0, sa45=0, sa67=0;
        u64 sb01=0, sb23=0, sb45=0, sb67=0;
        const float* kA = sK + lane*KSTRIDE;
        const float* kB = sK + (lane+32)*KSTRIDE;
        #pragma unroll 4
        for (int cb = 0; cb < 64; cb++) {
            float4 ka = *(const float4*)(kA + cb*4);
            float4 kb = *(const float4*)(kB + cb*4);
            #pragma unroll
            for (int cc = 0; cc < 4; cc++) {
                const float* qp = qb + (cb*4 + cc)*QTSTRIDE;
                ulonglong2 q03 = *(const ulonglong2*)qp;        // rows (0,1),(2,3)
                ulonglong2 q47 = *(const ulonglong2*)(qp + 4);  // rows (4,5),(6,7)
                float kaf = cc==0 ? ka.x : cc==1 ? ka.y : cc==2 ? ka.z : ka.w;
                float kbf = cc==0 ? kb.x : cc==1 ? kb.y : cc==2 ? kb.z : kb.w;
                u64 kka = pack2(kaf, kaf);
                u64 kkb = pack2(kbf, kbf);
                fma2(sa01, q03.x, kka); fma2(sa23, q03.y, kka);
                fma2(sa45, q47.x, kka); fma2(sa67, q47.y, kka);
                fma2(sb01, q03.x, kkb); fma2(sb23, q03.y, kkb);
                fma2(sb45, q47.x, kkb); fma2(sb67, q47.y, kkb);
            }
        }
        float sa[8], sb[8];
        unpack2(sa01, sa[0], sa[1]); unpack2(sa23, sa[2], sa[3]);
        unpack2(sa45, sa[4], sa[5]); unpack2(sa67, sa[6], sa[7]);
        unpack2(sb01, sb[0], sb[1]); unpack2(sb23, sb[2], sb[3]);
        unpack2(sb45, sb[4], sb[5]); unpack2(sb67, sb[6], sb[7]);

        // ---- online softmax (max via butterfly; sum folded into PV) ----
        float pa[8], pb[8], al[8];
        #pragma unroll
        for (int r = 0; r < 8; r++) {
            float mx = fmaxf(sa[r], sb[r]);
            #pragma unroll
            for (int o = 16; o; o >>= 1)
                mx = fmaxf(mx, __shfl_xor_sync(0xffffffffu, mx, o));
            float mn = fmaxf(m[r], mx);
            al[r] = __expf(m[r] - mn);
            m[r]  = mn;
            pa[r] = __expf(sa[r] - mn);
            pb[r] = __expf(sb[r] - mn);
        }
        #pragma unroll
        for (int rp = 0; rp < 4; rp++) {
            u64 aa = pack2(al[2*rp], al[2*rp+1]);
            #pragma unroll
            for (int j = 0; j < 8; j++) mul2(acc2[rp][j], aa);
            mul2(accl[rp], aa);
        }

        // ---- publish p to per-warp sP (conflict-free .128) ----
        *(float4*)&sPw[lane*PSTRIDE]          = make_float4(pa[0],pa[1],pa[2],pa[3]);
        *(float4*)&sPw[lane*PSTRIDE + 4]      = make_float4(pa[4],pa[5],pa[6],pa[7]);
        *(float4*)&sPw[(lane+32)*PSTRIDE]     = make_float4(pb[0],pb[1],pb[2],pb[3]);
        *(float4*)&sPw[(lane+32)*PSTRIDE + 4] = make_float4(pb[4],pb[5],pb[6],pb[7]);
        __syncwarp();

        // ---- P*V (+ fold row-sums into accl) ----
        #pragma unroll 2
        for (int s2 = 0; s2 < KEYS; s2++) {
            ulonglong2 p03 = *(const ulonglong2*)&sPw[s2*PSTRIDE];      // (p0,p1),(p2,p3)
            ulonglong2 p47 = *(const ulonglong2*)&sPw[s2*PSTRIDE + 4];  // (p4,p5),(p6,p7)
            float4 v0 = *(const float4*)(sK + s2*KSTRIDE + lane*4);
            float4 v1 = *(const float4*)(sK + s2*KSTRIDE + 128 + lane*4);
            float vf[8] = {v0.x, v0.y, v0.z, v0.w, v1.x, v1.y, v1.z, v1.w};
            #pragma unroll
            for (int j = 0; j < 8; j++) {
                u64 vd = pack2(vf[j], vf[j]);
                fma2(acc2[0][j], p03.x, vd);
                fma2(acc2[1][j], p03.y, vd);
                fma2(acc2[2][j], p47.x, vd);
                fma2(acc2[3][j], p47.y, vd);
            }
            add2(accl[0], p03.x); add2(accl[1], p03.y);
            add2(accl[2], p47.x); add2(accl[3], p47.y);
        }

        __syncthreads();   // all warps done reading sK[p&1]

        // prefetch pass p+2 into the buffer just freed
        if (p + 2 < NPASS) {
            uint32_t sb_ = (p & 1) ? sku1 : sku0;
            const float* gp = imgbase + (size_t)(2*(p+2))*HSTRIDE;
            #pragma unroll
            for (int k = 0; k < 16; k++) {
                int r = r0 + 4*k;
                cp16(sb_ + (r*KSTRIDE + cpc)*4,
                     gp + (size_t)(r >> 5)*HSTRIDE + (r & 31)*CC + cpc);
            }
        }
        CP_COMMIT();
    }

    // ---- epilogue: normalize and store ----
    #pragma unroll
    for (int rp = 0; rp < 4; rp++) {
        float l0, l1;
        unpack2(accl[rp], l0, l1);
        float lo[8], hi[8];
        #pragma unroll
        for (int j = 0; j < 8; j++) unpack2(acc2[rp][j], lo[j], hi[j]);
        int q0 = qtile*ROWS + warp*8 + 2*rp;
        if (q0 < NQ) {
            float inv = 1.0f / l0;
            size_t base = ((size_t)region*NQ + q0)*CC;
            *(float4*)&out[base + lane*4] =
                make_float4(lo[0]*inv, lo[1]*inv, lo[2]*inv, lo[3]*inv);
            *(float4*)&out[base + 128 + lane*4] =
                make_float4(lo[4]*inv, lo[5]*inv, lo[6]*inv, lo[7]*inv);
        }
        if (q0 + 1 < NQ) {
            float inv = 1.0f / l1;
            size_t base = ((size_t)region*NQ + q0 + 1)*CC;
            *(float4*)&out[base + lane*4] =
                make_float4(hi[0]*inv, hi[1]*inv, hi[2]*inv, hi[3]*inv);
            *(float4*)&out[base + 128 + lane*4] =
                make_float4(hi[4]*inv, hi[5]*inv, hi[6]*inv, hi[7]*inv);
        }
    }
}

// ---------------- positions (second tuple output) ----------------
__global__ void pos_kernel(float* __restrict__ out, int out_size) {
    int t = threadIdx.x;
    if (t < NREG && out_size >= OUT_ELEMS + POS_ELEMS) {
        out[OUT_ELEMS + 2*t + 0] = (float)(t / GDIM) * (1.0f / 7.0f);
        out[OUT_ELEMS + 2*t + 1] = (float)(t % GDIM) * (1.0f / 7.0f);
    }
}

extern "C" void kernel_launch(void* const* d_in, const int* in_sizes, int n_in,
                              void* d_out, int out_size) {
    const float* images  = (const float*)d_in[0];
    const float* queries = (const float*)d_in[1];
    if (n_in >= 2 && in_sizes[0] == NQ*CC) {
        const float* t = images; images = queries; queries = t;
    }
    float* out = (float*)d_out;

    cudaFuncSetAttribute(attn_kernel,
                         cudaFuncAttributeMaxDynamicSharedMemorySize, SMEM_BYTES);

    // pos_kernel first so ncu "-s 5 -c 1" lands on attn_kernel
    pos_kernel<<<1, 64>>>(out, out_size);
    attn_kernel<<<196*2, THREADS, SMEM_BYTES>>>(images, queries, out);
}

// round 9
// speedup vs baseline: 2.2287x; 2.2287x over previous
#include <cuda_runtime.h>
#include <cuda_bf16.h>
#include <cstdint>

#define NB 4
#define GDIM 7
#define NREG 49
#define HH 224
#define CC 256
#define NQ 100
#define HSTRIDE (HH*CC)
#define THREADS 128
#define NPASS 16            // 64 keys per pass
#define PAD 264             // bf16 row stride (528B -> conflict-free ldmatrix)

#define OUT_ELEMS (NB*NREG*NQ*CC)
#define POS_ELEMS (NREG*2)

// smem byte offsets
#define SQ_HI 0
#define SQ_LO 33792         // 64*264*2
#define SK_HI 67584
#define SK_LO 101376
#define SMEM_BYTES 135168
#define HILO 33792          // SK_LO - SK_HI

// ---------------- helpers ----------------
__device__ __forceinline__ uint32_t smem_u32(const void* p) {
    uint32_t a;
    asm("{ .reg .u64 t; cvta.to.shared.u64 t, %1; cvt.u32.u64 %0, t; }" : "=r"(a) : "l"(p));
    return a;
}
__device__ __forceinline__ uint32_t cvt2(float a, float b) {  // {lo=a, hi=b}
    uint32_t r; asm("cvt.rn.bf16x2.f32 %0, %2, %1;" : "=r"(r) : "f"(a), "f"(b));
    return r;
}
__device__ __forceinline__ void split2(float a, float b, uint32_t& hi, uint32_t& lo) {
    hi = cvt2(a, b);
    float ah = __uint_as_float(hi << 16);
    float bh = __uint_as_float(hi & 0xFFFF0000u);
    lo = cvt2(a - ah, b - bh);
}
__device__ __forceinline__ void ldsm4(uint32_t r[4], uint32_t a) {
    asm volatile("ldmatrix.sync.aligned.m8n8.x4.shared.b16 {%0,%1,%2,%3}, [%4];"
        : "=r"(r[0]), "=r"(r[1]), "=r"(r[2]), "=r"(r[3]) : "r"(a));
}
__device__ __forceinline__ void ldsm4t(uint32_t r[4], uint32_t a) {
    asm volatile("ldmatrix.sync.aligned.m8n8.x4.trans.shared.b16 {%0,%1,%2,%3}, [%4];"
        : "=r"(r[0]), "=r"(r[1]), "=r"(r[2]), "=r"(r[3]) : "r"(a));
}
__device__ __forceinline__ void mma16816(float* c, const uint32_t* a, uint32_t b0, uint32_t b1) {
    asm volatile("mma.sync.aligned.m16n8k16.row.col.f32.bf16.bf16.f32 "
        "{%0,%1,%2,%3}, {%4,%5,%6,%7}, {%8,%9}, {%0,%1,%2,%3};"
        : "+f"(c[0]), "+f"(c[1]), "+f"(c[2]), "+f"(c[3])
        : "r"(a[0]), "r"(a[1]), "r"(a[2]), "r"(a[3]), "r"(b0), "r"(b1));
}

// ================= kernel =================
// grid = 392 (196 regions x 2 q-tiles of 64 rows), 128 threads (4 warps x 16 rows)
__global__ void __launch_bounds__(THREADS, 1)
attn_kernel(const float* __restrict__ images,
            const float* __restrict__ queries,
            float* __restrict__ out)
{
    extern __shared__ char smem[];
    const uint32_t sa = smem_u32(smem);

    const int bx     = blockIdx.x;
    const int region = bx >> 1;
    const int qtile  = bx & 1;
    const int b  = region / NREG;
    const int n  = region % NREG;
    const int gi = n / GDIM;
    const int gj = n % GDIM;

    const int tid  = threadIdx.x;
    const int lane = tid & 31;
    const int warp = tid >> 5;          // 0..3, rows warp*16..warp*16+15

    // ---- stage Q hi/lo: [64 rows][PAD] bf16 each ----
    for (int id = tid; id < 64 * 128; id += THREADS) {   // channel pairs
        int q = id >> 7;
        int c = (id & 127) * 2;
        int qg = qtile * 64 + q;
        float x = 0.0f, y = 0.0f;
        if (qg < NQ) {
            float2 v = *(const float2*)&queries[qg * CC + c];
            x = v.x; y = v.y;
        }
        uint32_t h, l;
        split2(x, y, h, l);
        uint32_t o = (q * PAD + c) * 2;
        *(uint32_t*)(smem + SQ_HI + o) = h;
        *(uint32_t*)(smem + SQ_LO + o) = l;
    }

    // ---- per-lane ldmatrix base addresses ----
    // Q A-frags (normal): lanes -> rows (lane&15), col half (lane>>4)*8
    const uint32_t qA = sa + SQ_HI +
        (((warp * 16) + (lane & 15)) * PAD + (lane >> 4) * 8) * 2;
    // K B-frags (normal): row (lane&7)+(lane>>4)*8, col ((lane>>3)&1)*8
    const uint32_t kB = sa + SK_HI +
        (((lane & 7) + (lane >> 4) * 8) * PAD + ((lane >> 3) & 1) * 8) * 2;
    // V B-frags (trans): row (lane&7)+((lane>>3)&1)*8, col (lane>>4)*8
    const uint32_t vB = sa + SK_HI +
        (((lane & 7) + ((lane >> 3) & 1) * 8) * PAD + (lane >> 4) * 8) * 2;

    const float* imgbase = images + ((size_t)(b * HH + gi * 32) * HH + gj * 32) * CC;

    // ---- state ----
    float acc[32][4];                   // O [16 rows x 256 ch] fragment
    #pragma unroll
    for (int j = 0; j < 32; j++)
        #pragma unroll
        for (int k = 0; k < 4; k++) acc[j][k] = 0.0f;
    float m1 = -1e30f, m2 = -1e30f, l1 = 0.0f, l2 = 0.0f;

    for (int p = 0; p < NPASS; p++) {
        // ---- load 64 keys (2 image rows) as f32, convert, store hi/lo ----
        float4 v[32];
        {
            const float* g0 = imgbase + (size_t)(2 * p) * HSTRIDE;
            #pragma unroll
            for (int it = 0; it < 32; it++) {
                int id = tid + it * THREADS;       // 0..4095
                int s = id >> 6, c4 = id & 63;
                v[it] = *(const float4*)(g0 + (size_t)(s >> 5) * HSTRIDE
                                            + (s & 31) * CC + c4 * 4);
            }
        }
        __syncthreads();                // prev pass compute done
        #pragma unroll
        for (int it = 0; it < 32; it++) {
            int id = tid + it * THREADS;
            int s = id >> 6, c4 = id & 63;
            uint32_t h0, l0, h1, l1_;
            split2(v[it].x, v[it].y, h0, l0);
            split2(v[it].z, v[it].w, h1, l1_);
            uint32_t o = (s * PAD + c4 * 4) * 2;
            *(uint2*)(smem + SK_HI + o) = make_uint2(h0, h1);
            *(uint2*)(smem + SK_LO + o) = make_uint2(l0, l1_);
        }
        __syncthreads();

        // ---- QK: S[16 x 64] fragments, 3-term bf16 emulation ----
        float s_[8][4];
        #pragma unroll
        for (int j = 0; j < 8; j++)
            #pragma unroll
            for (int k = 0; k < 4; k++) s_[j][k] = 0.0f;

        #pragma unroll
        for (int ks = 0; ks < 16; ks++) {
            uint32_t ah[4], al[4];
            ldsm4(ah, qA + ks * 32);
            ldsm4(al, qA + HILO + ks * 32);
            #pragma unroll
            for (int j = 0; j < 4; j++) {          // 16 keys per iter
                uint32_t bh[4], bl[4];
                uint32_t ko = kB + j * (16 * PAD * 2) + ks * 32;
                ldsm4(bh, ko);
                ldsm4(bl, ko + HILO);
                mma16816(s_[2*j],   ah, bh[0], bh[1]);
                mma16816(s_[2*j],   ah, bl[0], bl[1]);
                mma16816(s_[2*j],   al, bh[0], bh[1]);
                mma16816(s_[2*j+1], ah, bh[2], bh[3]);
                mma16816(s_[2*j+1], ah, bl[2], bl[3]);
                mma16816(s_[2*j+1], al, bh[2], bh[3]);
            }
        }

        // ---- online softmax (rows r=lane>>2 and r+8) ----
        float mx1 = -1e30f, mx2 = -1e30f;
        #pragma unroll
        for (int j = 0; j < 8; j++) {
            mx1 = fmaxf(mx1, fmaxf(s_[j][0], s_[j][1]));
            mx2 = fmaxf(mx2, fmaxf(s_[j][2], s_[j][3]));
        }
        mx1 = fmaxf(mx1, __shfl_xor_sync(0xffffffffu, mx1, 1));
        mx1 = fmaxf(mx1, __shfl_xor_sync(0xffffffffu, mx1, 2));
        mx2 = fmaxf(mx2, __shfl_xor_sync(0xffffffffu, mx2, 1));
        mx2 = fmaxf(mx2, __shfl_xor_sync(0xffffffffu, mx2, 2));
        float m1n = fmaxf(m1, mx1), m2n = fmaxf(m2, mx2);
        float a1 = __expf(m1 - m1n), a2 = __expf(m2 - m2n);
        m1 = m1n; m2 = m2n;

        float sum1 = 0.0f, sum2 = 0.0f;
        #pragma unroll
        for (int j = 0; j < 8; j++) {
            s_[j][0] = __expf(s_[j][0] - m1); sum1 += s_[j][0];
            s_[j][1] = __expf(s_[j][1] - m1); sum1 += s_[j][1];
            s_[j][2] = __expf(s_[j][2] - m2); sum2 += s_[j][2];
            s_[j][3] = __expf(s_[j][3] - m2); sum2 += s_[j][3];
        }
        l1 = l1 * a1 + sum1;
        l2 = l2 * a2 + sum2;

        #pragma unroll
        for (int j = 0; j < 32; j++) {
            acc[j][0] *= a1; acc[j][1] *= a1;
            acc[j][2] *= a2; acc[j][3] *= a2;
        }

        // ---- pack P into PV A-fragments (C->A layout identity) ----
        uint32_t pAh[4][4], pAl[4][4];
        #pragma unroll
        for (int kk = 0; kk < 4; kk++) {
            split2(s_[2*kk][0],   s_[2*kk][1],   pAh[kk][0], pAl[kk][0]);
            split2(s_[2*kk][2],   s_[2*kk][3],   pAh[kk][1], pAl[kk][1]);
            split2(s_[2*kk+1][0], s_[2*kk+1][1], pAh[kk][2], pAl[kk][2]);
            split2(s_[2*kk+1][2], s_[2*kk+1][3], pAh[kk][3], pAl[kk][3]);
        }

        // ---- PV: O += P[16x64] * V[64x256], 3-term ----
        #pragma unroll
        for (int nn = 0; nn < 16; nn++) {
            #pragma unroll
            for (int kk = 0; kk < 4; kk++) {
                uint32_t bh[4], bl[4];
                uint32_t vo = vB + (kk * 16 * PAD + nn * 16) * 2;
                ldsm4t(bh, vo);
                ldsm4t(bl, vo + HILO);
                mma16816(acc[2*nn],   pAh[kk], bh[0], bh[1]);
                mma16816(acc[2*nn],   pAh[kk], bl[0], bl[1]);
                mma16816(acc[2*nn],   pAl[kk], bh[0], bh[1]);
                mma16816(acc[2*nn+1], pAh[kk], bh[2], bh[3]);
                mma16816(acc[2*nn+1], pAh[kk], bl[2], bl[3]);
                mma16816(acc[2*nn+1], pAl[kk], bh[2], bh[3]);
            }
        }
    }

    // ---- epilogue ----
    l1 += __shfl_xor_sync(0xffffffffu, l1, 1);
    l1 += __shfl_xor_sync(0xffffffffu, l1, 2);
    l2 += __shfl_xor_sync(0xffffffffu, l2, 1);
    l2 += __shfl_xor_sync(0xffffffffu, l2, 2);
    float inv1 = 1.0f / l1, inv2 = 1.0f / l2;

    int r1 = qtile * 64 + warp * 16 + (lane >> 2);
    int r2 = r1 + 8;
    int cb = 2 * (lane & 3);
    if (r1 < NQ) {
        float* o1 = out + ((size_t)region * NQ + r1) * CC + cb;
        #pragma unroll
        for (int j = 0; j < 32; j++)
            *(float2*)(o1 + j * 8) = make_float2(acc[j][0] * inv1, acc[j][1] * inv1);
    }
    if (r2 < NQ) {
        float* o2 = out + ((size_t)region * NQ + r2) * CC + cb;
        #pragma unroll
        for (int j = 0; j < 32; j++)
            *(float2*)(o2 + j * 8) = make_float2(acc[j][2] * inv2, acc[j][3] * inv2);
    }
}

// ---------------- positions (second tuple output) ----------------
__global__ void pos_kernel(float* __restrict__ out, int out_size) {
    int t = threadIdx.x;
    if (t < NREG && out_size >= OUT_ELEMS + POS_ELEMS) {
        out[OUT_ELEMS + 2 * t + 0] = (float)(t / GDIM) * (1.0f / 7.0f);
        out[OUT_ELEMS + 2 * t + 1] = (float)(t % GDIM) * (1.0f / 7.0f);
    }
}

extern "C" void kernel_launch(void* const* d_in, const int* in_sizes, int n_in,
                              void* d_out, int out_size) {
    const float* images  = (const float*)d_in[0];
    const float* queries = (const float*)d_in[1];
    if (n_in >= 2 && in_sizes[0] == NQ * CC) {
        const float* t = images; images = queries; queries = t;
    }
    float* out = (float*)d_out;

    cudaFuncSetAttribute(attn_kernel,
                         cudaFuncAttributeMaxDynamicSharedMemorySize, SMEM_BYTES);

    // pos_kernel first so ncu "-s 5 -c 1" lands on attn_kernel
    pos_kernel<<<1, 64>>>(out, out_size);
    attn_kernel<<<196 * 2, THREADS, SMEM_BYTES>>>(images, queries, out);
}

// round 10
// speedup vs baseline: 2.5197x; 1.1305x over previous
#include <cuda_runtime.h>
#include <cuda_bf16.h>
#include <cstdint>

#define NB 4
#define GDIM 7
#define NREG 49
#define HH 224
#define CC 256
#define NQ 100
#define HSTRIDE (HH*CC)
#define THREADS 128
#define NPASS 32            // 32 keys per pass (one image row-strip)
#define PAD 264             // bf16 row stride (528B -> conflict-free ldmatrix)

#define OUT_ELEMS (NB*NREG*NQ*CC)
#define POS_ELEMS (NREG*2)

// smem byte offsets
#define SQ_HI 0
#define SQ_LO 33792         // 64*264*2
#define SK_HI 67584
#define SK_LO 84480         // SK_HI + 32*264*2
#define SMEM_BYTES 101376   // 2 CTAs/SM: 202752 <= 227328
#define QHILO 33792
#define KHILO 16896

// ---------------- helpers ----------------
__device__ __forceinline__ uint32_t smem_u32(const void* p) {
    uint32_t a;
    asm("{ .reg .u64 t; cvta.to.shared.u64 t, %1; cvt.u32.u64 %0, t; }" : "=r"(a) : "l"(p));
    return a;
}
__device__ __forceinline__ uint32_t cvt2(float a, float b) {  // {lo=a, hi=b}
    uint32_t r; asm("cvt.rn.bf16x2.f32 %0, %2, %1;" : "=r"(r) : "f"(a), "f"(b));
    return r;
}
__device__ __forceinline__ void split2(float a, float b, uint32_t& hi, uint32_t& lo) {
    hi = cvt2(a, b);
    float ah = __uint_as_float(hi << 16);
    float bh = __uint_as_float(hi & 0xFFFF0000u);
    lo = cvt2(a - ah, b - bh);
}
__device__ __forceinline__ void ldsm4(uint32_t r[4], uint32_t a) {
    asm volatile("ldmatrix.sync.aligned.m8n8.x4.shared.b16 {%0,%1,%2,%3}, [%4];"
        : "=r"(r[0]), "=r"(r[1]), "=r"(r[2]), "=r"(r[3]) : "r"(a));
}
__device__ __forceinline__ void ldsm4t(uint32_t r[4], uint32_t a) {
    asm volatile("ldmatrix.sync.aligned.m8n8.x4.trans.shared.b16 {%0,%1,%2,%3}, [%4];"
        : "=r"(r[0]), "=r"(r[1]), "=r"(r[2]), "=r"(r[3]) : "r"(a));
}
__device__ __forceinline__ void mma16816(float* c, const uint32_t* a, uint32_t b0, uint32_t b1) {
    asm volatile("mma.sync.aligned.m16n8k16.row.col.f32.bf16.bf16.f32 "
        "{%0,%1,%2,%3}, {%4,%5,%6,%7}, {%8,%9}, {%0,%1,%2,%3};"
        : "+f"(c[0]), "+f"(c[1]), "+f"(c[2]), "+f"(c[3])
        : "r"(a[0]), "r"(a[1]), "r"(a[2]), "r"(a[3]), "r"(b0), "r"(b1));
}

// ================= kernel =================
// grid = 392 (196 regions x 2 q-tiles of 64 rows), 128 threads (4 warps x 16 rows)
// 2 CTAs resident per SM (smem 101376B x2 <= 227KB; regs <=255 x256 thr = RF)
__global__ void __launch_bounds__(THREADS, 2)
attn_kernel(const float* __restrict__ images,
            const float* __restrict__ queries,
            float* __restrict__ out)
{
    extern __shared__ char smem[];
    const uint32_t sa = smem_u32(smem);

    const int bx     = blockIdx.x;
    const int region = bx >> 1;
    const int qtile  = bx & 1;
    const int b  = region / NREG;
    const int n  = region % NREG;
    const int gi = n / GDIM;
    const int gj = n % GDIM;

    const int tid  = threadIdx.x;
    const int lane = tid & 31;
    const int warp = tid >> 5;          // 0..3, rows warp*16..warp*16+15

    // ---- stage Q hi/lo: [64 rows][PAD] bf16 each ----
    for (int id = tid; id < 64 * 128; id += THREADS) {   // channel pairs
        int q = id >> 7;
        int c = (id & 127) * 2;
        int qg = qtile * 64 + q;
        float x = 0.0f, y = 0.0f;
        if (qg < NQ) {
            float2 v = *(const float2*)&queries[qg * CC + c];
            x = v.x; y = v.y;
        }
        uint32_t h, l;
        split2(x, y, h, l);
        uint32_t o = (q * PAD + c) * 2;
        *(uint32_t*)(smem + SQ_HI + o) = h;
        *(uint32_t*)(smem + SQ_LO + o) = l;
    }

    // ---- per-lane ldmatrix base addresses ----
    const uint32_t qA = sa + SQ_HI +
        (((warp * 16) + (lane & 15)) * PAD + (lane >> 4) * 8) * 2;
    const uint32_t kB = sa + SK_HI +
        (((lane & 7) + (lane >> 4) * 8) * PAD + ((lane >> 3) & 1) * 8) * 2;
    const uint32_t vB = sa + SK_HI +
        (((lane & 7) + ((lane >> 3) & 1) * 8) * PAD + (lane >> 4) * 8) * 2;

    const float* imgbase = images + ((size_t)(b * HH + gi * 32) * HH + gj * 32) * CC;

    // ---- state ----
    float acc[32][4];                   // O [16 rows x 256 ch] fragment
    #pragma unroll
    for (int j = 0; j < 32; j++)
        #pragma unroll
        for (int k = 0; k < 4; k++) acc[j][k] = 0.0f;
    float m1 = -1e30f, m2 = -1e30f, l1 = 0.0f, l2 = 0.0f;

    for (int p = 0; p < NPASS; p++) {
        // ---- load 32 keys (one contiguous row-strip), convert, store hi/lo ----
        float4 v[16];
        {
            const float4* g0 = (const float4*)(imgbase + (size_t)p * HSTRIDE);
            #pragma unroll
            for (int it = 0; it < 16; it++) v[it] = g0[tid + it * THREADS];
        }
        __syncthreads();                // prev pass compute done
        #pragma unroll
        for (int it = 0; it < 16; it++) {
            int id = tid + it * THREADS;       // 0..2047
            int s = id >> 6, c4 = id & 63;
            uint32_t h0, l0, h1, l1_;
            split2(v[it].x, v[it].y, h0, l0);
            split2(v[it].z, v[it].w, h1, l1_);
            uint32_t o = (s * PAD + c4 * 4) * 2;
            *(uint2*)(smem + SK_HI + o) = make_uint2(h0, h1);
            *(uint2*)(smem + SK_LO + o) = make_uint2(l0, l1_);
        }
        __syncthreads();

        // ---- QK: S[16 x 32] fragments, 3-term bf16 emulation ----
        float s_[4][4];
        #pragma unroll
        for (int j = 0; j < 4; j++)
            #pragma unroll
            for (int k = 0; k < 4; k++) s_[j][k] = 0.0f;

        #pragma unroll
        for (int ks = 0; ks < 16; ks++) {
            uint32_t ah[4], al[4];
            ldsm4(ah, qA + ks * 32);
            ldsm4(al, qA + QHILO + ks * 32);
            #pragma unroll
            for (int j = 0; j < 2; j++) {          // 16 keys per iter
                uint32_t bh[4], bl[4];
                uint32_t ko = kB + j * (16 * PAD * 2) + ks * 32;
                ldsm4(bh, ko);
                ldsm4(bl, ko + KHILO);
                mma16816(s_[2*j],   ah, bh[0], bh[1]);
                mma16816(s_[2*j],   ah, bl[0], bl[1]);
                mma16816(s_[2*j],   al, bh[0], bh[1]);
                mma16816(s_[2*j+1], ah, bh[2], bh[3]);
                mma16816(s_[2*j+1], ah, bl[2], bl[3]);
                mma16816(s_[2*j+1], al, bh[2], bh[3]);
            }
        }

        // ---- online softmax (rows r=lane>>2 and r+8) ----
        float mx1 = -1e30f, mx2 = -1e30f;
        #pragma unroll
        for (int j = 0; j < 4; j++) {
            mx1 = fmaxf(mx1, fmaxf(s_[j][0], s_[j][1]));
            mx2 = fmaxf(mx2, fmaxf(s_[j][2], s_[j][3]));
        }
        mx1 = fmaxf(mx1, __shfl_xor_sync(0xffffffffu, mx1, 1));
        mx1 = fmaxf(mx1, __shfl_xor_sync(0xffffffffu, mx1, 2));
        mx2 = fmaxf(mx2, __shfl_xor_sync(0xffffffffu, mx2, 1));
        mx2 = fmaxf(mx2, __shfl_xor_sync(0xffffffffu, mx2, 2));
        float m1n = fmaxf(m1, mx1), m2n = fmaxf(m2, mx2);
        float a1 = __expf(m1 - m1n), a2 = __expf(m2 - m2n);
        m1 = m1n; m2 = m2n;

        float sum1 = 0.0f, sum2 = 0.0f;
        #pragma unroll
        for (int j = 0; j < 4; j++) {
            s_[j][0] = __expf(s_[j][0] - m1); sum1 += s_[j][0];
            s_[j][1] = __expf(s_[j][1] - m1); sum1 += s_[j][1];
            s_[j][2] = __expf(s_[j][2] - m2); sum2 += s_[j][2];
            s_[j][3] = __expf(s_[j][3] - m2); sum2 += s_[j][3];
        }
        l1 = l1 * a1 + sum1;
        l2 = l2 * a2 + sum2;

        #pragma unroll
        for (int j = 0; j < 32; j++) {
            acc[j][0] *= a1; acc[j][1] *= a1;
            acc[j][2] *= a2; acc[j][3] *= a2;
        }

        // ---- pack P into PV A-fragments (C->A layout identity) ----
        uint32_t pAh[2][4], pAl[2][4];
        #pragma unroll
        for (int kk = 0; kk < 2; kk++) {
            split2(s_[2*kk][0],   s_[2*kk][1],   pAh[kk][0], pAl[kk][0]);
            split2(s_[2*kk][2],   s_[2*kk][3],   pAh[kk][1], pAl[kk][1]);
            split2(s_[2*kk+1][0], s_[2*kk+1][1], pAh[kk][2], pAl[kk][2]);
            split2(s_[2*kk+1][2], s_[2*kk+1][3], pAh[kk][3], pAl[kk][3]);
        }

        // ---- PV: O += P[16x32] * V[32x256], 3-term ----
        #pragma unroll
        for (int nn = 0; nn < 16; nn++) {
            #pragma unroll
            for (int kk = 0; kk < 2; kk++) {
                uint32_t bh[4], bl[4];
                uint32_t vo = vB + (kk * 16 * PAD + nn * 16) * 2;
                ldsm4t(bh, vo);
                ldsm4t(bl, vo + KHILO);
                mma16816(acc[2*nn],   pAh[kk], bh[0], bh[1]);
                mma16816(acc[2*nn],   pAh[kk], bl[0], bl[1]);
                mma16816(acc[2*nn],   pAl[kk], bh[0], bh[1]);
                mma16816(acc[2*nn+1], pAh[kk], bh[2], bh[3]);
                mma16816(acc[2*nn+1], pAh[kk], bl[2], bl[3]);
                mma16816(acc[2*nn+1], pAl[kk], bh[2], bh[3]);
            }
        }
    }

    // ---- epilogue ----
    l1 += __shfl_xor_sync(0xffffffffu, l1, 1);
    l1 += __shfl_xor_sync(0xffffffffu, l1, 2);
    l2 += __shfl_xor_sync(0xffffffffu, l2, 1);
    l2 += __shfl_xor_sync(0xffffffffu, l2, 2);
    float inv1 = 1.0f / l1, inv2 = 1.0f / l2;

    int r1 = qtile * 64 + warp * 16 + (lane >> 2);
    int r2 = r1 + 8;
    int cb = 2 * (lane & 3);
    if (r1 < NQ) {
        float* o1 = out + ((size_t)region * NQ + r1) * CC + cb;
        #pragma unroll
        for (int j = 0; j < 32; j++)
            *(float2*)(o1 + j * 8) = make_float2(acc[j][0] * inv1, acc[j][1] * inv1);
    }
    if (r2 < NQ) {
        float* o2 = out + ((size_t)region * NQ + r2) * CC + cb;
        #pragma unroll
        for (int j = 0; j < 32; j++)
            *(float2*)(o2 + j * 8) = make_float2(acc[j][2] * inv2, acc[j][3] * inv2);
    }
}

// ---------------- positions (second tuple output) ----------------
__global__ void pos_kernel(float* __restrict__ out, int out_size) {
    int t = threadIdx.x;
    if (t < NREG && out_size >= OUT_ELEMS + POS_ELEMS) {
        out[OUT_ELEMS + 2 * t + 0] = (float)(t / GDIM) * (1.0f / 7.0f);
        out[OUT_ELEMS + 2 * t + 1] = (float)(t % GDIM) * (1.0f / 7.0f);
    }
}

extern "C" void kernel_launch(void* const* d_in, const int* in_sizes, int n_in,
                              void* d_out, int out_size) {
    const float* images  = (const float*)d_in[0];
    const float* queries = (const float*)d_in[1];
    if (n_in >= 2 && in_sizes[0] == NQ * CC) {
        const float* t = images; images = queries; queries = t;
    }
    float* out = (float*)d_out;

    cudaFuncSetAttribute(attn_kernel,
                         cudaFuncAttributeMaxDynamicSharedMemorySize, SMEM_BYTES);

    // pos_kernel first so ncu "-s 5 -c 1" lands on attn_kernel
    pos_kernel<<<1, 64>>>(out, out_size);
    attn_kernel<<<196 * 2, THREADS, SMEM_BYTES>>>(images, queries, out);
}